// round 14
// baseline (speedup 1.0000x reference)
#include <cuda_runtime.h>
#include <cuda_bf16.h>
#include <cstdint>

#define NN 50000
#define NE 320000
#define HID 256
#define NLAYERS 5
#define BN_EPS 1e-5f
#define NB_SCAN ((NN + 255) / 256)   // 196
#define NBY ((NN + 127) / 128)       // 391

// ---------------- scratch (device globals; no allocation allowed) -------------
__device__ float g_h[(size_t)NN * HID];          // fp32 h (for agg gather)
__device__ float g_tmp[(size_t)NN * HID];        // pre-BN activations
__device__ __nv_bfloat16 g_hh[(size_t)NN * HID]; // h split hi (GEMM A, k<256)
__device__ __nv_bfloat16 g_hl[(size_t)NN * HID]; // h split lo
__device__ __nv_bfloat16 g_gh[(size_t)NN * HID]; // agg split hi (GEMM A, k>=256)
__device__ __nv_bfloat16 g_gl[(size_t)NN * HID]; // agg split lo
__device__ __nv_bfloat16 g_wh[(size_t)NLAYERS * 256 * 512]; // W^T hi [l][n][k]
__device__ __nv_bfloat16 g_wl[(size_t)NLAYERS * 256 * 512]; // W^T lo
__device__ float g_dinv[NN];
__device__ int   g_degi[NN];
__device__ int   g_off[NN + 1];
__device__ int   g_cur[NN];
__device__ int   g_row[NE];
__device__ float g_nrm[NE];
__device__ float g_S[(size_t)NN * 4];
__device__ float g_cs[HID];
__device__ float g_cs2[HID];
__device__ int   g_part[256];
__device__ int   g_is64;

// ---------------- helpers ------------------------------------------------------
__device__ __forceinline__ uint32_t smem_u32(const void* p) {
    uint32_t a;
    asm("{ .reg .u64 t; cvta.to.shared.u64 t, %1; cvt.u32.u64 %0, t; }"
        : "=r"(a) : "l"(p));
    return a;
}
__device__ __forceinline__ uint32_t bfpack(float a, float b) {
    __nv_bfloat162 t = __floats2bfloat162_rn(a, b);
    return *reinterpret_cast<uint32_t*>(&t);
}
__device__ __forceinline__ void bfsplit(float v, float& h, float& l) {
    h = __bfloat162float(__float2bfloat16_rn(v));
    l = v - h;
}
__device__ __forceinline__ void cpa16(uint32_t dst, const void* src) {
    asm volatile("cp.async.cg.shared.global [%0], [%1], 16;"
                 :: "r"(dst), "l"(src) : "memory");
}

// ---------------- edge-index dtype detection ----------------------------------
__global__ void detect_kernel(const int* __restrict__ ei32) {
    __shared__ int nz;
    if (threadIdx.x == 0) nz = 0;
    __syncthreads();
    int cnt = 0;
    for (int i = threadIdx.x; i < 4096; i += blockDim.x)
        if (ei32[2 * i + 1] != 0) cnt++;
    atomicAdd(&nz, cnt);
    __syncthreads();
    if (threadIdx.x == 0) g_is64 = (nz == 0) ? 1 : 0;
}

__device__ __forceinline__ int fetch_idx(const void* ei, int part, int e) {
    int v;
    if (g_is64) v = (int)((const long long*)ei)[(size_t)part * NE + e];
    else        v = ((const int*)ei)[(size_t)part * NE + e];
    return (v < 0 || v >= NN) ? 0 : v;
}

// ---------------- CSR build ---------------------------------------------------
__global__ void zero_init_kernel() {
    int i = blockIdx.x * blockDim.x + threadIdx.x;
    if (i < NN) { g_degi[i] = 0; g_cur[i] = 0; }
    if (i < NN * 4) g_S[i] = 0.0f;
}

__global__ void count_kernel(const void* __restrict__ ei) {
    int e = blockIdx.x * blockDim.x + threadIdx.x;
    if (e < NE) atomicAdd(&g_degi[fetch_idx(ei, 1, e)], 1);
}

__global__ void scan1_kernel() {
    __shared__ int sh[256];
    int i = blockIdx.x * 256 + threadIdx.x;
    int v = (i < NN) ? g_degi[i] : 0;
    sh[threadIdx.x] = v;
    __syncthreads();
    for (int s = 128; s > 0; s >>= 1) {
        if (threadIdx.x < s) sh[threadIdx.x] += sh[threadIdx.x + s];
        __syncthreads();
    }
    if (threadIdx.x == 0) g_part[blockIdx.x] = sh[0];
}

__global__ void scan2_kernel() {
    __shared__ int sh[256];
    int t = threadIdx.x;
    sh[t] = (t < NB_SCAN) ? g_part[t] : 0;
    __syncthreads();
    for (int off = 1; off < 256; off <<= 1) {
        int v = (t >= off) ? sh[t - off] : 0;
        __syncthreads();
        sh[t] += v;
        __syncthreads();
    }
    g_part[t] = (t == 0) ? 0 : sh[t - 1];
}

__global__ void scan3_kernel() {
    __shared__ int sh[256];
    int t = threadIdx.x;
    int i = blockIdx.x * 256 + t;
    int v = (i < NN) ? g_degi[i] : 0;
    sh[t] = v;
    __syncthreads();
    for (int off = 1; off < 256; off <<= 1) {
        int x = (t >= off) ? sh[t - off] : 0;
        __syncthreads();
        sh[t] += x;
        __syncthreads();
    }
    int excl = sh[t] - v + g_part[blockIdx.x];
    if (i < NN) {
        g_off[i] = excl;
        g_dinv[i] = (v > 0) ? rsqrtf((float)v) : 0.0f;
        if (i == NN - 1) g_off[NN] = excl + v;
    }
}

__global__ void fill_kernel(const void* __restrict__ ei) {
    int e = blockIdx.x * blockDim.x + threadIdx.x;
    if (e < NE) {
        int r = fetch_idx(ei, 0, e);
        int c = fetch_idx(ei, 1, e);
        int p = atomicAdd(&g_cur[c], 1);
        int slot = g_off[c] + p;
        if (slot >= 0 && slot < NE) {
            g_row[slot] = r;
            g_nrm[slot] = g_dinv[r] * g_dinv[c];
        }
    }
}

__global__ void sedge_kernel(const void* __restrict__ ei,
                             const float* __restrict__ ea) {
    int e = blockIdx.x * blockDim.x + threadIdx.x;
    if (e < NE) {
        int r = fetch_idx(ei, 0, e);
        int c = fetch_idx(ei, 1, e);
        float nrm = g_dinv[r] * g_dinv[c];
        float4 v = *(const float4*)(ea + (size_t)e * 4);
        float* s = g_S + (size_t)c * 4;
        atomicAdd(s + 0, nrm * v.x);
        atomicAdd(s + 1, nrm * v.y);
        atomicAdd(s + 2, nrm * v.z);
        atomicAdd(s + 3, nrm * v.w);
    }
}

// ---------------- one-time split kernels ---------------------------------------
__global__ void wsplit_kernel(const float* __restrict__ mlp_w) {
    int idx = blockIdx.x * blockDim.x + threadIdx.x;
    if (idx >= NLAYERS * 512 * 256) return;
    int n = idx & 255;
    int k = (idx >> 8) & 511;
    int l = idx >> 17;
    float h, lo;
    bfsplit(mlp_w[idx], h, lo);
    size_t o = ((size_t)l * 256 + n) * 512 + k;
    g_wh[o] = __float2bfloat16_rn(h);
    g_wl[o] = __float2bfloat16_rn(lo);
}

__global__ void xsplit_kernel(const float* __restrict__ x) {
    int idx = blockIdx.x * blockDim.x + threadIdx.x;
    if (idx >= NN * HID / 4) return;
    float4 v = ((const float4*)x)[idx];
    float h0, l0, h1, l1, h2, l2, h3, l3;
    bfsplit(v.x, h0, l0); bfsplit(v.y, h1, l1);
    bfsplit(v.z, h2, l2); bfsplit(v.w, h3, l3);
    ((uint2*)g_hh)[idx] = make_uint2(bfpack(h0, h1), bfpack(h2, h3));
    ((uint2*)g_hl)[idx] = make_uint2(bfpack(l0, l1), bfpack(l2, l3));
}

// ---------------- aggregation: warp/node (R11-proven fp32 gather) --------------
__global__ void __launch_bounds__(256) agg_kernel(
    const float* __restrict__ x_ext, int use_ext,
    const float* __restrict__ ew1, const float* __restrict__ ew2)
{
    int node = (blockIdx.x * blockDim.x + threadIdx.x) >> 5;
    int ln = threadIdx.x & 31;
    if (node >= NN) return;

    const float* hin = use_ext ? x_ext : g_h;

    float acc[8];
#pragma unroll
    for (int q = 0; q < 8; q++) acc[q] = 0.0f;

    int s = g_off[node];
    int e_end = g_off[node + 1];
    for (int i = s; i < e_end; i++) {
        int r = g_row[i];
        float nrm = g_nrm[i];
        const float* hr = hin + (size_t)r * HID + ln * 8;
        float4 v0 = __ldg((const float4*)hr);
        float4 v1 = __ldg((const float4*)(hr + 4));
        acc[0] = fmaf(nrm, v0.x, acc[0]);
        acc[1] = fmaf(nrm, v0.y, acc[1]);
        acc[2] = fmaf(nrm, v0.z, acc[2]);
        acc[3] = fmaf(nrm, v0.w, acc[3]);
        acc[4] = fmaf(nrm, v1.x, acc[4]);
        acc[5] = fmaf(nrm, v1.y, acc[5]);
        acc[6] = fmaf(nrm, v1.z, acc[6]);
        acc[7] = fmaf(nrm, v1.w, acc[7]);
    }

    float4 S = *(const float4*)(g_S + (size_t)node * 4);
    float hi[8], lo[8];
#pragma unroll
    for (int q = 0; q < 8; q++) {
        int j = ln * 8 + q;
        float fea;
        if (j < 128) {
            fea = S.w * ew1[j];
        } else {
            int jj = j - 128;
            fea = fmaf(S.x, ew2[jj], fmaf(S.y, ew2[128 + jj], S.z * ew2[256 + jj]));
        }
        bfsplit(acc[q] + fea, hi[q], lo[q]);
    }
    uint4 ph = make_uint4(bfpack(hi[0], hi[1]), bfpack(hi[2], hi[3]),
                          bfpack(hi[4], hi[5]), bfpack(hi[6], hi[7]));
    uint4 pl = make_uint4(bfpack(lo[0], lo[1]), bfpack(lo[2], lo[3]),
                          bfpack(lo[4], lo[5]), bfpack(lo[6], lo[7]));
    ((uint4*)g_gh)[node * 32 + ln] = ph;
    ((uint4*)g_gl)[node * 32 + ln] = pl;
}

// ================= bf16x3 tensor-core GEMM (R11-best config) ===================
// g_tmp = relu([h, agg] @ W + b).  grid (2, 391), 256 thr, 2-stage cp.async.

#define APITCH 80
#define STG    40960
#define SMEM_DYN (2 * STG)   // 81920

#define LDSM4(r0, r1, r2, r3, addr)                                            \
    asm volatile("ldmatrix.sync.aligned.m8n8.x4.shared.b16 {%0,%1,%2,%3}, [%4];" \
                 : "=r"(r0), "=r"(r1), "=r"(r2), "=r"(r3) : "r"(addr))

#define MMA16(d, a, b0, b1)                                                    \
    asm volatile(                                                              \
        "mma.sync.aligned.m16n8k16.row.col.f32.bf16.bf16.f32 "                 \
        "{%0,%1,%2,%3}, {%4,%5,%6,%7}, {%8,%9}, {%0,%1,%2,%3};"                \
        : "+f"(d[0]), "+f"(d[1]), "+f"(d[2]), "+f"(d[3])                       \
        : "r"(a[0]), "r"(a[1]), "r"(a[2]), "r"(a[3]), "r"(b0), "r"(b1))

__device__ __forceinline__ void stage_chunk(
    uint32_t base, int c, int rowBase, int colBase,
    const __nv_bfloat16* __restrict__ Wh, const __nv_bfloat16* __restrict__ Wl,
    int tid)
{
    const __nv_bfloat16* Ah = (c < 8) ? g_hh : g_gh;
    const __nv_bfloat16* Al = (c < 8) ? g_hl : g_gl;
    int ka = (c & 7) * 32;
    int k0 = c * 32;
#pragma unroll
    for (int t = 0; t < 2; t++) {
        int idx = tid + t * 256;
        int row = idx >> 2, seg = idx & 3;
        int gr = rowBase + row;
        if (gr >= NN) gr = NN - 1;
        uint32_t so = (uint32_t)(row * APITCH + seg * 16);
        const size_t ao = (size_t)gr * 256 + ka + seg * 8;
        cpa16(base + so,         Ah + ao);
        cpa16(base + 10240 + so, Al + ao);
        const size_t bo = (size_t)(colBase + row) * 512 + k0 + seg * 8;
        cpa16(base + 20480 + so, Wh + bo);
        cpa16(base + 30720 + so, Wl + bo);
    }
}

__global__ void __launch_bounds__(256, 2) gemm_bf(
    int layer, const float* __restrict__ mlp_b)
{
    extern __shared__ char dsm[];
    const __nv_bfloat16* Wh = g_wh + (size_t)layer * 256 * 512;
    const __nv_bfloat16* Wl = g_wl + (size_t)layer * 256 * 512;
    const float* bias = mlp_b + (size_t)layer * 256;

    int tid = threadIdx.x;
    int wid = tid >> 5, lane = tid & 31;
    int gid = lane >> 2, tig = lane & 3;
    int warp_m = wid >> 2, warp_n = wid & 3;
    int rowBase = blockIdx.y * 128;
    int colBase = blockIdx.x * 128;
    uint32_t sbase = smem_u32(dsm);

    float acc[4][4][4];
#pragma unroll
    for (int mi = 0; mi < 4; mi++)
#pragma unroll
        for (int ni = 0; ni < 4; ni++)
#pragma unroll
            for (int q = 0; q < 4; q++) acc[mi][ni][q] = 0.0f;

    stage_chunk(sbase, 0, rowBase, colBase, Wh, Wl, tid);
    asm volatile("cp.async.commit_group;");

    for (int c = 0; c < 16; c++) {
        int p = c & 1;
        if (c < 15) {
            stage_chunk(sbase + (1 - p) * STG, c + 1, rowBase, colBase, Wh, Wl, tid);
            asm volatile("cp.async.commit_group;");
            asm volatile("cp.async.wait_group 1;");
        } else {
            asm volatile("cp.async.wait_group 0;");
        }
        __syncthreads();

        uint32_t sA  = sbase + p * STG;
        uint32_t sAL = sA + 10240;
        uint32_t sB  = sA + 20480;
        uint32_t sBL = sA + 30720;
#pragma unroll
        for (int s = 0; s < 2; s++) {
            int kb = s * 16;
            uint32_t aH4[4][4], aL4[4][4], bH2[4][2], bL2[4][2];
            int rla = (lane & 15);
            int kha = (kb + ((lane >> 4) << 3)) * 2;
#pragma unroll
            for (int mi = 0; mi < 4; mi++) {
                uint32_t off = (uint32_t)((warp_m * 64 + mi * 16 + rla) * APITCH) + kha;
                LDSM4(aH4[mi][0], aH4[mi][1], aH4[mi][2], aH4[mi][3], sA + off);
                LDSM4(aL4[mi][0], aL4[mi][1], aL4[mi][2], aL4[mi][3], sAL + off);
            }
            int nlb = (lane & 7) + ((lane >> 4) << 3);
            int klb = (kb + (((lane >> 3) & 1) << 3)) * 2;
#pragma unroll
            for (int j = 0; j < 2; j++) {
                uint32_t off = (uint32_t)((warp_n * 32 + j * 16 + nlb) * APITCH) + klb;
                LDSM4(bH2[2 * j][0], bH2[2 * j][1], bH2[2 * j + 1][0], bH2[2 * j + 1][1], sB + off);
                LDSM4(bL2[2 * j][0], bL2[2 * j][1], bL2[2 * j + 1][0], bL2[2 * j + 1][1], sBL + off);
            }
#pragma unroll
            for (int mi = 0; mi < 4; mi++)
#pragma unroll
                for (int ni = 0; ni < 4; ni++) {
                    MMA16(acc[mi][ni], aH4[mi], bL2[ni][0], bL2[ni][1]);
                    MMA16(acc[mi][ni], aL4[mi], bH2[ni][0], bH2[ni][1]);
                    MMA16(acc[mi][ni], aH4[mi], bH2[ni][0], bH2[ni][1]);
                }
        }
        __syncthreads();
    }

    // epilogue: bias + relu -> g_tmp
#pragma unroll
    for (int mi = 0; mi < 4; mi++) {
        int r0 = rowBase + warp_m * 64 + mi * 16 + gid;
        int r1 = r0 + 8;
#pragma unroll
        for (int ni = 0; ni < 4; ni++) {
            int col = colBase + warp_n * 32 + ni * 8 + tig * 2;
            float b0 = __ldg(bias + col), b1 = __ldg(bias + col + 1);
            if (r0 < NN) {
                float2 v;
                v.x = fmaxf(acc[mi][ni][0] + b0, 0.0f);
                v.y = fmaxf(acc[mi][ni][1] + b1, 0.0f);
                *(float2*)(g_tmp + (size_t)r0 * 256 + col) = v;
            }
            if (r1 < NN) {
                float2 v;
                v.x = fmaxf(acc[mi][ni][2] + b0, 0.0f);
                v.y = fmaxf(acc[mi][ni][3] + b1, 0.0f);
                *(float2*)(g_tmp + (size_t)r1 * 256 + col) = v;
            }
        }
    }
}

// ---------------- BatchNorm (R11-proven) ---------------------------------------
__global__ void zero_stats_kernel() {
    int t = threadIdx.x;
    if (t < HID) g_cs[t] = 0.0f;
    else if (t < 2 * HID) g_cs2[t - HID] = 0.0f;
}

__global__ void __launch_bounds__(256) bnstat_kernel() {
    int c = threadIdx.x;
    int r0 = blockIdx.x * 128;
    int r1 = min(r0 + 128, NN);
    float s = 0.0f, s2 = 0.0f;
    for (int r = r0; r < r1; r++) {
        float v = g_tmp[(size_t)r * HID + c];
        s += v;
        s2 += v * v;
    }
    atomicAdd(&g_cs[c], s);
    atomicAdd(&g_cs2[c], s2);
}

__global__ void __launch_bounds__(256) bnapply_kernel(
    float* __restrict__ out_ext, int use_ext,
    const float* __restrict__ gamma, const float* __restrict__ beta, int dorelu)
{
    int idx = blockIdx.x * blockDim.x + threadIdx.x;
    if (idx >= NN * HID / 4) return;
    float* O = use_ext ? out_ext : g_h;
    int c4 = idx & 63;
    const float invn = 1.0f / (float)NN;
    float4 cs  = ((const float4*)g_cs)[c4];
    float4 cs2 = ((const float4*)g_cs2)[c4];
    float4 gm  = ((const float4*)gamma)[c4];
    float4 bt  = ((const float4*)beta)[c4];
    float4 xv  = ((const float4*)g_tmp)[idx];
    float4 ov;
    {
        float mu = cs.x * invn, var = cs2.x * invn - mu * mu;
        ov.x = (xv.x - mu) * rsqrtf(var + BN_EPS) * gm.x + bt.x;
        mu = cs.y * invn; var = cs2.y * invn - mu * mu;
        ov.y = (xv.y - mu) * rsqrtf(var + BN_EPS) * gm.y + bt.y;
        mu = cs.z * invn; var = cs2.z * invn - mu * mu;
        ov.z = (xv.z - mu) * rsqrtf(var + BN_EPS) * gm.z + bt.z;
        mu = cs.w * invn; var = cs2.w * invn - mu * mu;
        ov.w = (xv.w - mu) * rsqrtf(var + BN_EPS) * gm.w + bt.w;
    }
    if (dorelu) {
        ov.x = fmaxf(ov.x, 0.0f); ov.y = fmaxf(ov.y, 0.0f);
        ov.z = fmaxf(ov.z, 0.0f); ov.w = fmaxf(ov.w, 0.0f);
    }
    ((float4*)O)[idx] = ov;
    if (!use_ext) {  // feed next layer's GEMM: bf16 hi/lo splits
        float h0, l0, h1, l1, h2, l2, h3, l3;
        bfsplit(ov.x, h0, l0); bfsplit(ov.y, h1, l1);
        bfsplit(ov.z, h2, l2); bfsplit(ov.w, h3, l3);
        ((uint2*)g_hh)[idx] = make_uint2(bfpack(h0, h1), bfpack(h2, h3));
        ((uint2*)g_hl)[idx] = make_uint2(bfpack(l0, l1), bfpack(l2, l3));
    }
}

// ---------------- launch ------------------------------------------------------
extern "C" void kernel_launch(void* const* d_in, const int* in_sizes, int n_in,
                              void* d_out, int out_size) {
    const float* x     = (const float*)d_in[0];
    const void*  ei    = d_in[1];
    const float* ea    = (const float*)d_in[2];
    const float* mlp_w = (const float*)d_in[3];
    const float* mlp_b = (const float*)d_in[4];
    const float* ew1   = (const float*)d_in[5];
    const float* ew2   = (const float*)d_in[6];
    const float* bn_g  = (const float*)d_in[7];
    const float* bn_b  = (const float*)d_in[8];
    float* out = (float*)d_out;

    cudaFuncSetAttribute(gemm_bf, cudaFuncAttributeMaxDynamicSharedMemorySize,
                         SMEM_DYN);

    detect_kernel<<<1, 256>>>((const int*)ei);            // idx 0
    zero_init_kernel<<<(NN * 4 + 255) / 256, 256>>>();    // idx 1
    count_kernel<<<(NE + 255) / 256, 256>>>(ei);          // idx 2
    // DIAGNOSTIC launch at idx 3 (the slot ncu -s 5 -c 1 captures): the real
    // GEMM on steady-state operands. Writes only g_tmp, which layer-0's real
    // gemm_bf overwrites before any consumer — result-invariant, deterministic.
    {
        dim3 ggrid(2, NBY);
        gemm_bf<<<ggrid, 256, SMEM_DYN>>>(0, mlp_b);      // idx 3 (profiled)
    }
    scan1_kernel<<<NB_SCAN, 256>>>();                     // idx 4
    scan2_kernel<<<1, 256>>>();
    scan3_kernel<<<NB_SCAN, 256>>>();
    fill_kernel<<<(NE + 255) / 256, 256>>>(ei);
    sedge_kernel<<<(NE + 255) / 256, 256>>>(ei, ea);
    wsplit_kernel<<<(NLAYERS * 512 * 256 + 255) / 256, 256>>>(mlp_w);
    xsplit_kernel<<<(NN * HID / 4 + 255) / 256, 256>>>(x);

    for (int l = 0; l < NLAYERS; l++) {
        int first = (l == 0) ? 1 : 0;
        int last  = (l == NLAYERS - 1) ? 1 : 0;

        agg_kernel<<<(NN * 32 + 255) / 256, 256>>>(
            x, first, ew1 + (size_t)l * 128, ew2 + (size_t)l * 3 * 128);

        dim3 ggrid(2, NBY);
        gemm_bf<<<ggrid, 256, SMEM_DYN>>>(l, mlp_b);

        zero_stats_kernel<<<1, 512>>>();
        bnstat_kernel<<<(NN + 127) / 128, 256>>>();
        bnapply_kernel<<<(NN * HID / 4 + 255) / 256, 256>>>(
            out, last, bn_g + (size_t)l * 256, bn_b + (size_t)l * 256, last ? 0 : 1);
    }
}

// round 16
// speedup vs baseline: 1.1278x; 1.1278x over previous
#include <cuda_runtime.h>
#include <cuda_bf16.h>
#include <cstdint>

#define NN 50000
#define NE 320000
#define HID 256
#define NLAYERS 5
#define BN_EPS 1e-5f
#define NB_SCAN ((NN + 255) / 256)   // 196
#define NBY ((NN + 127) / 128)       // 391

// ---------------- scratch (device globals; no allocation allowed) -------------
__device__ float g_h[(size_t)NN * HID];          // fp32 h (for agg gather)
__device__ float g_tmp[(size_t)NN * HID];        // pre-BN activations
__device__ __nv_bfloat16 g_hh[(size_t)NN * HID]; // h split hi (GEMM A, k<256)
__device__ __nv_bfloat16 g_hl[(size_t)NN * HID]; // h split lo
__device__ __nv_bfloat16 g_gh[(size_t)NN * HID]; // agg split hi (GEMM A, k>=256)
__device__ __nv_bfloat16 g_gl[(size_t)NN * HID]; // agg split lo
__device__ __nv_bfloat16 g_wh[(size_t)NLAYERS * 256 * 512]; // W^T hi [l][n][k]
__device__ __nv_bfloat16 g_wl[(size_t)NLAYERS * 256 * 512]; // W^T lo
__device__ float g_dinv[NN];
__device__ int   g_degi[NN];
__device__ int   g_off[NN + 1];
__device__ int   g_cur[NN];
__device__ int   g_row[NE];
__device__ float g_nrm[NE];
__device__ float g_S[(size_t)NN * 4];
__device__ float g_cs[HID];
__device__ float g_cs2[HID];
__device__ int   g_part[256];
__device__ int   g_is64;

// ---------------- helpers ------------------------------------------------------
__device__ __forceinline__ uint32_t smem_u32(const void* p) {
    uint32_t a;
    asm("{ .reg .u64 t; cvta.to.shared.u64 t, %1; cvt.u32.u64 %0, t; }"
        : "=r"(a) : "l"(p));
    return a;
}
__device__ __forceinline__ uint32_t bfpack(float a, float b) {
    __nv_bfloat162 t = __floats2bfloat162_rn(a, b);
    return *reinterpret_cast<uint32_t*>(&t);
}
__device__ __forceinline__ void bfsplit(float v, float& h, float& l) {
    h = __bfloat162float(__float2bfloat16_rn(v));
    l = v - h;
}
__device__ __forceinline__ void cpa16(uint32_t dst, const void* src) {
    asm volatile("cp.async.cg.shared.global [%0], [%1], 16;"
                 :: "r"(dst), "l"(src) : "memory");
}

// ---------------- edge-index dtype detection ----------------------------------
__global__ void detect_kernel(const int* __restrict__ ei32) {
    __shared__ int nz;
    if (threadIdx.x == 0) nz = 0;
    __syncthreads();
    int cnt = 0;
    for (int i = threadIdx.x; i < 4096; i += blockDim.x)
        if (ei32[2 * i + 1] != 0) cnt++;
    atomicAdd(&nz, cnt);
    __syncthreads();
    if (threadIdx.x == 0) g_is64 = (nz == 0) ? 1 : 0;
}

__device__ __forceinline__ int fetch_idx(const void* ei, int part, int e) {
    int v;
    if (g_is64) v = (int)((const long long*)ei)[(size_t)part * NE + e];
    else        v = ((const int*)ei)[(size_t)part * NE + e];
    return (v < 0 || v >= NN) ? 0 : v;
}

// ---------------- CSR build ---------------------------------------------------
__global__ void zero_init_kernel() {
    int i = blockIdx.x * blockDim.x + threadIdx.x;
    if (i < NN) { g_degi[i] = 0; g_cur[i] = 0; }
    if (i < NN * 4) g_S[i] = 0.0f;
}

__global__ void count_kernel(const void* __restrict__ ei) {
    int e = blockIdx.x * blockDim.x + threadIdx.x;
    if (e < NE) atomicAdd(&g_degi[fetch_idx(ei, 1, e)], 1);
}

__global__ void scan1_kernel() {
    __shared__ int sh[256];
    int i = blockIdx.x * 256 + threadIdx.x;
    int v = (i < NN) ? g_degi[i] : 0;
    sh[threadIdx.x] = v;
    __syncthreads();
    for (int s = 128; s > 0; s >>= 1) {
        if (threadIdx.x < s) sh[threadIdx.x] += sh[threadIdx.x + s];
        __syncthreads();
    }
    if (threadIdx.x == 0) g_part[blockIdx.x] = sh[0];
}

__global__ void scan2_kernel() {
    __shared__ int sh[256];
    int t = threadIdx.x;
    sh[t] = (t < NB_SCAN) ? g_part[t] : 0;
    __syncthreads();
    for (int off = 1; off < 256; off <<= 1) {
        int v = (t >= off) ? sh[t - off] : 0;
        __syncthreads();
        sh[t] += v;
        __syncthreads();
    }
    g_part[t] = (t == 0) ? 0 : sh[t - 1];
}

__global__ void scan3_kernel() {
    __shared__ int sh[256];
    int t = threadIdx.x;
    int i = blockIdx.x * 256 + t;
    int v = (i < NN) ? g_degi[i] : 0;
    sh[t] = v;
    __syncthreads();
    for (int off = 1; off < 256; off <<= 1) {
        int x = (t >= off) ? sh[t - off] : 0;
        __syncthreads();
        sh[t] += x;
        __syncthreads();
    }
    int excl = sh[t] - v + g_part[blockIdx.x];
    if (i < NN) {
        g_off[i] = excl;
        g_dinv[i] = (v > 0) ? rsqrtf((float)v) : 0.0f;
        if (i == NN - 1) g_off[NN] = excl + v;
    }
}

__global__ void fill_kernel(const void* __restrict__ ei) {
    int e = blockIdx.x * blockDim.x + threadIdx.x;
    if (e < NE) {
        int r = fetch_idx(ei, 0, e);
        int c = fetch_idx(ei, 1, e);
        int p = atomicAdd(&g_cur[c], 1);
        int slot = g_off[c] + p;
        if (slot >= 0 && slot < NE) {
            g_row[slot] = r;
            g_nrm[slot] = g_dinv[r] * g_dinv[c];
        }
    }
}

__global__ void sedge_kernel(const void* __restrict__ ei,
                             const float* __restrict__ ea) {
    int e = blockIdx.x * blockDim.x + threadIdx.x;
    if (e < NE) {
        int r = fetch_idx(ei, 0, e);
        int c = fetch_idx(ei, 1, e);
        float nrm = g_dinv[r] * g_dinv[c];
        float4 v = *(const float4*)(ea + (size_t)e * 4);
        float* s = g_S + (size_t)c * 4;
        atomicAdd(s + 0, nrm * v.x);
        atomicAdd(s + 1, nrm * v.y);
        atomicAdd(s + 2, nrm * v.z);
        atomicAdd(s + 3, nrm * v.w);
    }
}

// ---------------- one-time split kernels ---------------------------------------
__global__ void wsplit_kernel(const float* __restrict__ mlp_w) {
    int idx = blockIdx.x * blockDim.x + threadIdx.x;
    if (idx >= NLAYERS * 512 * 256) return;
    int n = idx & 255;
    int k = (idx >> 8) & 511;
    int l = idx >> 17;
    float h, lo;
    bfsplit(mlp_w[idx], h, lo);
    size_t o = ((size_t)l * 256 + n) * 512 + k;
    g_wh[o] = __float2bfloat16_rn(h);
    g_wl[o] = __float2bfloat16_rn(lo);
}

__global__ void xsplit_kernel(const float* __restrict__ x) {
    int idx = blockIdx.x * blockDim.x + threadIdx.x;
    if (idx >= NN * HID / 4) return;
    float4 v = ((const float4*)x)[idx];
    float h0, l0, h1, l1, h2, l2, h3, l3;
    bfsplit(v.x, h0, l0); bfsplit(v.y, h1, l1);
    bfsplit(v.z, h2, l2); bfsplit(v.w, h3, l3);
    ((uint2*)g_hh)[idx] = make_uint2(bfpack(h0, h1), bfpack(h2, h3));
    ((uint2*)g_hl)[idx] = make_uint2(bfpack(l0, l1), bfpack(l2, l3));
}

// ---------------- aggregation: warp/node (R11-proven fp32 gather) --------------
__global__ void __launch_bounds__(256) agg_kernel(
    const float* __restrict__ x_ext, int use_ext,
    const float* __restrict__ ew1, const float* __restrict__ ew2)
{
    int node = (blockIdx.x * blockDim.x + threadIdx.x) >> 5;
    int ln = threadIdx.x & 31;
    if (node >= NN) return;

    const float* hin = use_ext ? x_ext : g_h;

    float acc[8];
#pragma unroll
    for (int q = 0; q < 8; q++) acc[q] = 0.0f;

    int s = g_off[node];
    int e_end = g_off[node + 1];
    for (int i = s; i < e_end; i++) {
        int r = g_row[i];
        float nrm = g_nrm[i];
        const float* hr = hin + (size_t)r * HID + ln * 8;
        float4 v0 = __ldg((const float4*)hr);
        float4 v1 = __ldg((const float4*)(hr + 4));
        acc[0] = fmaf(nrm, v0.x, acc[0]);
        acc[1] = fmaf(nrm, v0.y, acc[1]);
        acc[2] = fmaf(nrm, v0.z, acc[2]);
        acc[3] = fmaf(nrm, v0.w, acc[3]);
        acc[4] = fmaf(nrm, v1.x, acc[4]);
        acc[5] = fmaf(nrm, v1.y, acc[5]);
        acc[6] = fmaf(nrm, v1.z, acc[6]);
        acc[7] = fmaf(nrm, v1.w, acc[7]);
    }

    float4 S = *(const float4*)(g_S + (size_t)node * 4);
    float hi[8], lo[8];
#pragma unroll
    for (int q = 0; q < 8; q++) {
        int j = ln * 8 + q;
        float fea;
        if (j < 128) {
            fea = S.w * ew1[j];
        } else {
            int jj = j - 128;
            fea = fmaf(S.x, ew2[jj], fmaf(S.y, ew2[128 + jj], S.z * ew2[256 + jj]));
        }
        bfsplit(acc[q] + fea, hi[q], lo[q]);
    }
    uint4 ph = make_uint4(bfpack(hi[0], hi[1]), bfpack(hi[2], hi[3]),
                          bfpack(hi[4], hi[5]), bfpack(hi[6], hi[7]));
    uint4 pl = make_uint4(bfpack(lo[0], lo[1]), bfpack(lo[2], lo[3]),
                          bfpack(lo[4], lo[5]), bfpack(lo[6], lo[7]));
    ((uint4*)g_gh)[node * 32 + ln] = ph;
    ((uint4*)g_gl)[node * 32 + ln] = pl;
}

// ================= bf16x3 GEMM: 2-stage cp.async, ONE barrier per chunk ========
// g_tmp = relu([h, agg] @ W + b).  grid (2, 391), 256 thr, warp layout 2m x 4n.
// APITCH=80 (16B multiple: cp.async-16 alignment requirement).

#define APITCH 80
#define ABYTES (128 * APITCH)        // 10240 per array
#define STG    (4 * ABYTES)          // 40960 per stage
#define SMEM_DYN (2 * STG)           // 81920

#define LDSM4(r0, r1, r2, r3, addr)                                            \
    asm volatile("ldmatrix.sync.aligned.m8n8.x4.shared.b16 {%0,%1,%2,%3}, [%4];" \
                 : "=r"(r0), "=r"(r1), "=r"(r2), "=r"(r3) : "r"(addr))

#define MMA16(d, a, b0, b1)                                                    \
    asm volatile(                                                              \
        "mma.sync.aligned.m16n8k16.row.col.f32.bf16.bf16.f32 "                 \
        "{%0,%1,%2,%3}, {%4,%5,%6,%7}, {%8,%9}, {%0,%1,%2,%3};"                \
        : "+f"(d[0]), "+f"(d[1]), "+f"(d[2]), "+f"(d[3])                       \
        : "r"(a[0]), "r"(a[1]), "r"(a[2]), "r"(a[3]), "r"(b0), "r"(b1))

__device__ __forceinline__ void stage_chunk(
    uint32_t base, int c, int rowBase, int colBase,
    const __nv_bfloat16* __restrict__ Wh, const __nv_bfloat16* __restrict__ Wl,
    int tid)
{
    const __nv_bfloat16* Ah = (c < 8) ? g_hh : g_gh;
    const __nv_bfloat16* Al = (c < 8) ? g_hl : g_gl;
    int ka = (c & 7) * 32;
    int k0 = c * 32;
#pragma unroll
    for (int t = 0; t < 2; t++) {
        int idx = tid + t * 256;
        int row = idx >> 2, seg = idx & 3;
        int gr = rowBase + row;
        if (gr >= NN) gr = NN - 1;
        uint32_t so = (uint32_t)(row * APITCH + seg * 16);
        const size_t ao = (size_t)gr * 256 + ka + seg * 8;
        cpa16(base + so,              Ah + ao);
        cpa16(base + ABYTES + so,     Al + ao);
        const size_t bo = (size_t)(colBase + row) * 512 + k0 + seg * 8;
        cpa16(base + 2 * ABYTES + so, Wh + bo);
        cpa16(base + 3 * ABYTES + so, Wl + bo);
    }
}

__global__ void __launch_bounds__(256, 2) gemm_bf(
    int layer, const float* __restrict__ mlp_b)
{
    extern __shared__ char dsm[];
    const __nv_bfloat16* Wh = g_wh + (size_t)layer * 256 * 512;
    const __nv_bfloat16* Wl = g_wl + (size_t)layer * 256 * 512;
    const float* bias = mlp_b + (size_t)layer * 256;

    int tid = threadIdx.x;
    int wid = tid >> 5, lane = tid & 31;
    int gid = lane >> 2, tig = lane & 3;
    int warp_m = wid >> 2, warp_n = wid & 3;
    int rowBase = blockIdx.y * 128;
    int colBase = blockIdx.x * 128;
    uint32_t sbase = smem_u32(dsm);

    float acc[4][4][4];
#pragma unroll
    for (int mi = 0; mi < 4; mi++)
#pragma unroll
        for (int ni = 0; ni < 4; ni++)
#pragma unroll
            for (int q = 0; q < 4; q++) acc[mi][ni][q] = 0.0f;

    stage_chunk(sbase, 0, rowBase, colBase, Wh, Wl, tid);
    asm volatile("cp.async.commit_group;");

    for (int c = 0; c < 16; c++) {
        // chunk c is the only pending group -> wait for it
        asm volatile("cp.async.wait_group 0;");
        __syncthreads();   // ALSO proves all warps finished reading chunk c-1

        // stage c+1 into the buffer chunk c-1 just vacated; overlaps MMA below
        if (c + 1 < 16) {
            stage_chunk(sbase + ((c + 1) & 1) * STG, c + 1, rowBase, colBase,
                        Wh, Wl, tid);
            asm volatile("cp.async.commit_group;");
        }

        uint32_t sA  = sbase + (c & 1) * STG;
        uint32_t sAL = sA + ABYTES;
        uint32_t sB  = sA + 2 * ABYTES;
        uint32_t sBL = sA + 3 * ABYTES;
#pragma unroll
        for (int s = 0; s < 2; s++) {
            int kb = s * 16;
            uint32_t aH4[4][4], aL4[4][4], bH2[4][2], bL2[4][2];
            int rla = (lane & 15);
            int kha = (kb + ((lane >> 4) << 3)) * 2;
#pragma unroll
            for (int mi = 0; mi < 4; mi++) {
                uint32_t off = (uint32_t)((warp_m * 64 + mi * 16 + rla) * APITCH) + kha;
                LDSM4(aH4[mi][0], aH4[mi][1], aH4[mi][2], aH4[mi][3], sA + off);
                LDSM4(aL4[mi][0], aL4[mi][1], aL4[mi][2], aL4[mi][3], sAL + off);
            }
            int nlb = (lane & 7) + ((lane >> 4) << 3);
            int klb = (kb + (((lane >> 3) & 1) << 3)) * 2;
#pragma unroll
            for (int j = 0; j < 2; j++) {
                uint32_t off = (uint32_t)((warp_n * 32 + j * 16 + nlb) * APITCH) + klb;
                LDSM4(bH2[2 * j][0], bH2[2 * j][1], bH2[2 * j + 1][0], bH2[2 * j + 1][1], sB + off);
                LDSM4(bL2[2 * j][0], bL2[2 * j][1], bL2[2 * j + 1][0], bL2[2 * j + 1][1], sBL + off);
            }
#pragma unroll
            for (int mi = 0; mi < 4; mi++)
#pragma unroll
                for (int ni = 0; ni < 4; ni++) {
                    MMA16(acc[mi][ni], aH4[mi], bL2[ni][0], bL2[ni][1]);
                    MMA16(acc[mi][ni], aL4[mi], bH2[ni][0], bH2[ni][1]);
                    MMA16(acc[mi][ni], aH4[mi], bH2[ni][0], bH2[ni][1]);
                }
        }
    }

    // epilogue: bias + relu -> g_tmp (registers only; no barrier needed)
#pragma unroll
    for (int mi = 0; mi < 4; mi++) {
        int r0 = rowBase + warp_m * 64 + mi * 16 + gid;
        int r1 = r0 + 8;
#pragma unroll
        for (int ni = 0; ni < 4; ni++) {
            int col = colBase + warp_n * 32 + ni * 8 + tig * 2;
            float b0 = __ldg(bias + col), b1 = __ldg(bias + col + 1);
            if (r0 < NN) {
                float2 v;
                v.x = fmaxf(acc[mi][ni][0] + b0, 0.0f);
                v.y = fmaxf(acc[mi][ni][1] + b1, 0.0f);
                *(float2*)(g_tmp + (size_t)r0 * 256 + col) = v;
            }
            if (r1 < NN) {
                float2 v;
                v.x = fmaxf(acc[mi][ni][2] + b0, 0.0f);
                v.y = fmaxf(acc[mi][ni][3] + b1, 0.0f);
                *(float2*)(g_tmp + (size_t)r1 * 256 + col) = v;
            }
        }
    }
}

// ---------------- BatchNorm (R11-proven) ---------------------------------------
__global__ void zero_stats_kernel() {
    int t = threadIdx.x;
    if (t < HID) g_cs[t] = 0.0f;
    else if (t < 2 * HID) g_cs2[t - HID] = 0.0f;
}

__global__ void __launch_bounds__(256) bnstat_kernel() {
    int c = threadIdx.x;
    int r0 = blockIdx.x * 128;
    int r1 = min(r0 + 128, NN);
    float s = 0.0f, s2 = 0.0f;
    for (int r = r0; r < r1; r++) {
        float v = g_tmp[(size_t)r * HID + c];
        s += v;
        s2 += v * v;
    }
    atomicAdd(&g_cs[c], s);
    atomicAdd(&g_cs2[c], s2);
}

__global__ void __launch_bounds__(256) bnapply_kernel(
    float* __restrict__ out_ext, int use_ext,
    const float* __restrict__ gamma, const float* __restrict__ beta, int dorelu)
{
    int idx = blockIdx.x * blockDim.x + threadIdx.x;
    if (idx >= NN * HID / 4) return;
    float* O = use_ext ? out_ext : g_h;
    int c4 = idx & 63;
    const float invn = 1.0f / (float)NN;
    float4 cs  = ((const float4*)g_cs)[c4];
    float4 cs2 = ((const float4*)g_cs2)[c4];
    float4 gm  = ((const float4*)gamma)[c4];
    float4 bt  = ((const float4*)beta)[c4];
    float4 xv  = ((const float4*)g_tmp)[idx];
    float4 ov;
    {
        float mu = cs.x * invn, var = cs2.x * invn - mu * mu;
        ov.x = (xv.x - mu) * rsqrtf(var + BN_EPS) * gm.x + bt.x;
        mu = cs.y * invn; var = cs2.y * invn - mu * mu;
        ov.y = (xv.y - mu) * rsqrtf(var + BN_EPS) * gm.y + bt.y;
        mu = cs.z * invn; var = cs2.z * invn - mu * mu;
        ov.z = (xv.z - mu) * rsqrtf(var + BN_EPS) * gm.z + bt.z;
        mu = cs.w * invn; var = cs2.w * invn - mu * mu;
        ov.w = (xv.w - mu) * rsqrtf(var + BN_EPS) * gm.w + bt.w;
    }
    if (dorelu) {
        ov.x = fmaxf(ov.x, 0.0f); ov.y = fmaxf(ov.y, 0.0f);
        ov.z = fmaxf(ov.z, 0.0f); ov.w = fmaxf(ov.w, 0.0f);
    }
    ((float4*)O)[idx] = ov;
    if (!use_ext) {  // feed next layer's GEMM: bf16 hi/lo splits
        float h0, l0, h1, l1, h2, l2, h3, l3;
        bfsplit(ov.x, h0, l0); bfsplit(ov.y, h1, l1);
        bfsplit(ov.z, h2, l2); bfsplit(ov.w, h3, l3);
        ((uint2*)g_hh)[idx] = make_uint2(bfpack(h0, h1), bfpack(h2, h3));
        ((uint2*)g_hl)[idx] = make_uint2(bfpack(l0, l1), bfpack(l2, l3));
    }
}

// ---------------- launch ------------------------------------------------------
extern "C" void kernel_launch(void* const* d_in, const int* in_sizes, int n_in,
                              void* d_out, int out_size) {
    const float* x     = (const float*)d_in[0];
    const void*  ei    = d_in[1];
    const float* ea    = (const float*)d_in[2];
    const float* mlp_w = (const float*)d_in[3];
    const float* mlp_b = (const float*)d_in[4];
    const float* ew1   = (const float*)d_in[5];
    const float* ew2   = (const float*)d_in[6];
    const float* bn_g  = (const float*)d_in[7];
    const float* bn_b  = (const float*)d_in[8];
    float* out = (float*)d_out;

    cudaFuncSetAttribute(gemm_bf, cudaFuncAttributeMaxDynamicSharedMemorySize,
                         SMEM_DYN);

    detect_kernel<<<1, 256>>>((const int*)ei);
    zero_init_kernel<<<(NN * 4 + 255) / 256, 256>>>();
    count_kernel<<<(NE + 255) / 256, 256>>>(ei);
    scan1_kernel<<<NB_SCAN, 256>>>();
    scan2_kernel<<<1, 256>>>();
    scan3_kernel<<<NB_SCAN, 256>>>();
    fill_kernel<<<(NE + 255) / 256, 256>>>(ei);
    sedge_kernel<<<(NE + 255) / 256, 256>>>(ei, ea);
    wsplit_kernel<<<(NLAYERS * 512 * 256 + 255) / 256, 256>>>(mlp_w);
    xsplit_kernel<<<(NN * HID / 4 + 255) / 256, 256>>>(x);

    for (int l = 0; l < NLAYERS; l++) {
        int first = (l == 0) ? 1 : 0;
        int last  = (l == NLAYERS - 1) ? 1 : 0;

        agg_kernel<<<(NN * 32 + 255) / 256, 256>>>(
            x, first, ew1 + (size_t)l * 128, ew2 + (size_t)l * 3 * 128);

        dim3 ggrid(2, NBY);
        gemm_bf<<<ggrid, 256, SMEM_DYN>>>(l, mlp_b);

        zero_stats_kernel<<<1, 512>>>();
        bnstat_kernel<<<(NN + 127) / 128, 256>>>();
        bnapply_kernel<<<(NN * HID / 4 + 255) / 256, 256>>>(
            out, last, bn_g + (size_t)l * 256, bn_b + (size_t)l * 256, last ? 0 : 1);
    }
}

// round 17
// speedup vs baseline: 1.1442x; 1.0145x over previous
#include <cuda_runtime.h>
#include <cuda_bf16.h>
#include <cstdint>

#define NN 50000
#define NE 320000
#define HID 256
#define NLAYERS 5
#define BN_EPS 1e-5f
#define NB_SCAN ((NN + 255) / 256)   // 196
#define NBY ((NN + 127) / 128)       // 391

// ---------------- scratch (device globals; no allocation allowed) -------------
__device__ float g_h[(size_t)NN * HID];          // fp32 h (for agg gather)
__device__ float g_tmp[(size_t)NN * HID];        // pre-BN activations
__device__ __nv_bfloat16 g_hh[(size_t)NN * HID]; // h split hi (GEMM A, k<256)
__device__ __nv_bfloat16 g_hl[(size_t)NN * HID]; // h split lo
__device__ __nv_bfloat16 g_gh[(size_t)NN * HID]; // agg split hi (GEMM A, k>=256)
__device__ __nv_bfloat16 g_gl[(size_t)NN * HID]; // agg split lo
__device__ __nv_bfloat16 g_wh[(size_t)NLAYERS * 256 * 512]; // W^T hi [l][n][k]
__device__ __nv_bfloat16 g_wl[(size_t)NLAYERS * 256 * 512]; // W^T lo
__device__ float g_ps1[(size_t)NBY * 256];       // per-CTA-row column sums
__device__ float g_ps2[(size_t)NBY * 256];       // per-CTA-row column sumsq
__device__ float g_dinv[NN];
__device__ int   g_degi[NN];
__device__ int   g_off[NN + 1];
__device__ int   g_cur[NN];
__device__ int   g_row[NE];
__device__ float g_nrm[NE];
__device__ float g_S[(size_t)NN * 4];
__device__ float g_cs[HID];
__device__ float g_cs2[HID];
__device__ int   g_part[256];
__device__ int   g_is64;

// ---------------- helpers ------------------------------------------------------
__device__ __forceinline__ uint32_t smem_u32(const void* p) {
    uint32_t a;
    asm("{ .reg .u64 t; cvta.to.shared.u64 t, %1; cvt.u32.u64 %0, t; }"
        : "=r"(a) : "l"(p));
    return a;
}
__device__ __forceinline__ uint32_t bfpack(float a, float b) {
    __nv_bfloat162 t = __floats2bfloat162_rn(a, b);
    return *reinterpret_cast<uint32_t*>(&t);
}
__device__ __forceinline__ void bfsplit(float v, float& h, float& l) {
    h = __bfloat162float(__float2bfloat16_rn(v));
    l = v - h;
}
__device__ __forceinline__ void cpa16(uint32_t dst, const void* src) {
    asm volatile("cp.async.cg.shared.global [%0], [%1], 16;"
                 :: "r"(dst), "l"(src) : "memory");
}

// ---------------- edge-index dtype detection ----------------------------------
__global__ void detect_kernel(const int* __restrict__ ei32) {
    __shared__ int nz;
    if (threadIdx.x == 0) nz = 0;
    __syncthreads();
    int cnt = 0;
    for (int i = threadIdx.x; i < 4096; i += blockDim.x)
        if (ei32[2 * i + 1] != 0) cnt++;
    atomicAdd(&nz, cnt);
    __syncthreads();
    if (threadIdx.x == 0) g_is64 = (nz == 0) ? 1 : 0;
}

__device__ __forceinline__ int fetch_idx(const void* ei, int part, int e) {
    int v;
    if (g_is64) v = (int)((const long long*)ei)[(size_t)part * NE + e];
    else        v = ((const int*)ei)[(size_t)part * NE + e];
    return (v < 0 || v >= NN) ? 0 : v;
}

// ---------------- CSR build ---------------------------------------------------
__global__ void zero_init_kernel() {
    int i = blockIdx.x * blockDim.x + threadIdx.x;
    if (i < NN) { g_degi[i] = 0; g_cur[i] = 0; }
    if (i < NN * 4) g_S[i] = 0.0f;
}

__global__ void count_kernel(const void* __restrict__ ei) {
    int e = blockIdx.x * blockDim.x + threadIdx.x;
    if (e < NE) atomicAdd(&g_degi[fetch_idx(ei, 1, e)], 1);
}

__global__ void scan1_kernel() {
    __shared__ int sh[256];
    int i = blockIdx.x * 256 + threadIdx.x;
    int v = (i < NN) ? g_degi[i] : 0;
    sh[threadIdx.x] = v;
    __syncthreads();
    for (int s = 128; s > 0; s >>= 1) {
        if (threadIdx.x < s) sh[threadIdx.x] += sh[threadIdx.x + s];
        __syncthreads();
    }
    if (threadIdx.x == 0) g_part[blockIdx.x] = sh[0];
}

__global__ void scan2_kernel() {
    __shared__ int sh[256];
    int t = threadIdx.x;
    sh[t] = (t < NB_SCAN) ? g_part[t] : 0;
    __syncthreads();
    for (int off = 1; off < 256; off <<= 1) {
        int v = (t >= off) ? sh[t - off] : 0;
        __syncthreads();
        sh[t] += v;
        __syncthreads();
    }
    g_part[t] = (t == 0) ? 0 : sh[t - 1];
}

__global__ void scan3_kernel() {
    __shared__ int sh[256];
    int t = threadIdx.x;
    int i = blockIdx.x * 256 + t;
    int v = (i < NN) ? g_degi[i] : 0;
    sh[t] = v;
    __syncthreads();
    for (int off = 1; off < 256; off <<= 1) {
        int x = (t >= off) ? sh[t - off] : 0;
        __syncthreads();
        sh[t] += x;
        __syncthreads();
    }
    int excl = sh[t] - v + g_part[blockIdx.x];
    if (i < NN) {
        g_off[i] = excl;
        g_dinv[i] = (v > 0) ? rsqrtf((float)v) : 0.0f;
        if (i == NN - 1) g_off[NN] = excl + v;
    }
}

__global__ void fill_kernel(const void* __restrict__ ei) {
    int e = blockIdx.x * blockDim.x + threadIdx.x;
    if (e < NE) {
        int r = fetch_idx(ei, 0, e);
        int c = fetch_idx(ei, 1, e);
        int p = atomicAdd(&g_cur[c], 1);
        int slot = g_off[c] + p;
        if (slot >= 0 && slot < NE) {
            g_row[slot] = r;
            g_nrm[slot] = g_dinv[r] * g_dinv[c];
        }
    }
}

__global__ void sedge_kernel(const void* __restrict__ ei,
                             const float* __restrict__ ea) {
    int e = blockIdx.x * blockDim.x + threadIdx.x;
    if (e < NE) {
        int r = fetch_idx(ei, 0, e);
        int c = fetch_idx(ei, 1, e);
        float nrm = g_dinv[r] * g_dinv[c];
        float4 v = *(const float4*)(ea + (size_t)e * 4);
        float* s = g_S + (size_t)c * 4;
        atomicAdd(s + 0, nrm * v.x);
        atomicAdd(s + 1, nrm * v.y);
        atomicAdd(s + 2, nrm * v.z);
        atomicAdd(s + 3, nrm * v.w);
    }
}

// ---------------- one-time split kernels ---------------------------------------
__global__ void wsplit_kernel(const float* __restrict__ mlp_w) {
    int idx = blockIdx.x * blockDim.x + threadIdx.x;
    if (idx >= NLAYERS * 512 * 256) return;
    int n = idx & 255;
    int k = (idx >> 8) & 511;
    int l = idx >> 17;
    float h, lo;
    bfsplit(mlp_w[idx], h, lo);
    size_t o = ((size_t)l * 256 + n) * 512 + k;
    g_wh[o] = __float2bfloat16_rn(h);
    g_wl[o] = __float2bfloat16_rn(lo);
}

__global__ void xsplit_kernel(const float* __restrict__ x) {
    int idx = blockIdx.x * blockDim.x + threadIdx.x;
    if (idx >= NN * HID / 4) return;
    float4 v = ((const float4*)x)[idx];
    float h0, l0, h1, l1, h2, l2, h3, l3;
    bfsplit(v.x, h0, l0); bfsplit(v.y, h1, l1);
    bfsplit(v.z, h2, l2); bfsplit(v.w, h3, l3);
    ((uint2*)g_hh)[idx] = make_uint2(bfpack(h0, h1), bfpack(h2, h3));
    ((uint2*)g_hl)[idx] = make_uint2(bfpack(l0, l1), bfpack(l2, l3));
}

// ---------------- aggregation: warp/node (R11-proven fp32 gather) --------------
__global__ void __launch_bounds__(256) agg_kernel(
    const float* __restrict__ x_ext, int use_ext,
    const float* __restrict__ ew1, const float* __restrict__ ew2)
{
    int node = (blockIdx.x * blockDim.x + threadIdx.x) >> 5;
    int ln = threadIdx.x & 31;
    if (node >= NN) return;

    const float* hin = use_ext ? x_ext : g_h;

    float acc[8];
#pragma unroll
    for (int q = 0; q < 8; q++) acc[q] = 0.0f;

    int s = g_off[node];
    int e_end = g_off[node + 1];
    for (int i = s; i < e_end; i++) {
        int r = g_row[i];
        float nrm = g_nrm[i];
        const float* hr = hin + (size_t)r * HID + ln * 8;
        float4 v0 = __ldg((const float4*)hr);
        float4 v1 = __ldg((const float4*)(hr + 4));
        acc[0] = fmaf(nrm, v0.x, acc[0]);
        acc[1] = fmaf(nrm, v0.y, acc[1]);
        acc[2] = fmaf(nrm, v0.z, acc[2]);
        acc[3] = fmaf(nrm, v0.w, acc[3]);
        acc[4] = fmaf(nrm, v1.x, acc[4]);
        acc[5] = fmaf(nrm, v1.y, acc[5]);
        acc[6] = fmaf(nrm, v1.z, acc[6]);
        acc[7] = fmaf(nrm, v1.w, acc[7]);
    }

    float4 S = *(const float4*)(g_S + (size_t)node * 4);
    float hi[8], lo[8];
#pragma unroll
    for (int q = 0; q < 8; q++) {
        int j = ln * 8 + q;
        float fea;
        if (j < 128) {
            fea = S.w * ew1[j];
        } else {
            int jj = j - 128;
            fea = fmaf(S.x, ew2[jj], fmaf(S.y, ew2[128 + jj], S.z * ew2[256 + jj]));
        }
        bfsplit(acc[q] + fea, hi[q], lo[q]);
    }
    uint4 ph = make_uint4(bfpack(hi[0], hi[1]), bfpack(hi[2], hi[3]),
                          bfpack(hi[4], hi[5]), bfpack(hi[6], hi[7]));
    uint4 pl = make_uint4(bfpack(lo[0], lo[1]), bfpack(lo[2], lo[3]),
                          bfpack(lo[4], lo[5]), bfpack(lo[6], lo[7]));
    ((uint4*)g_gh)[node * 32 + ln] = ph;
    ((uint4*)g_gl)[node * 32 + ln] = pl;
}

// ================= bf16x3 GEMM: 2-stage cp.async, ONE barrier per chunk ========
// g_tmp = relu([h, agg] @ W + b); also emits per-CTA BN column partials.

#define APITCH 80
#define ABYTES (128 * APITCH)        // 10240 per array
#define STG    (4 * ABYTES)          // 40960 per stage
#define SMEM_DYN (2 * STG)           // 81920

#define LDSM4(r0, r1, r2, r3, addr)                                            \
    asm volatile("ldmatrix.sync.aligned.m8n8.x4.shared.b16 {%0,%1,%2,%3}, [%4];" \
                 : "=r"(r0), "=r"(r1), "=r"(r2), "=r"(r3) : "r"(addr))

#define MMA16(d, a, b0, b1)                                                    \
    asm volatile(                                                              \
        "mma.sync.aligned.m16n8k16.row.col.f32.bf16.bf16.f32 "                 \
        "{%0,%1,%2,%3}, {%4,%5,%6,%7}, {%8,%9}, {%0,%1,%2,%3};"                \
        : "+f"(d[0]), "+f"(d[1]), "+f"(d[2]), "+f"(d[3])                       \
        : "r"(a[0]), "r"(a[1]), "r"(a[2]), "r"(a[3]), "r"(b0), "r"(b1))

__device__ __forceinline__ void stage_chunk(
    uint32_t base, int c, int rowBase, int colBase,
    const __nv_bfloat16* __restrict__ Wh, const __nv_bfloat16* __restrict__ Wl,
    int tid)
{
    const __nv_bfloat16* Ah = (c < 8) ? g_hh : g_gh;
    const __nv_bfloat16* Al = (c < 8) ? g_hl : g_gl;
    int ka = (c & 7) * 32;
    int k0 = c * 32;
#pragma unroll
    for (int t = 0; t < 2; t++) {
        int idx = tid + t * 256;
        int row = idx >> 2, seg = idx & 3;
        int gr = rowBase + row;
        if (gr >= NN) gr = NN - 1;
        uint32_t so = (uint32_t)(row * APITCH + seg * 16);
        const size_t ao = (size_t)gr * 256 + ka + seg * 8;
        cpa16(base + so,              Ah + ao);
        cpa16(base + ABYTES + so,     Al + ao);
        const size_t bo = (size_t)(colBase + row) * 512 + k0 + seg * 8;
        cpa16(base + 2 * ABYTES + so, Wh + bo);
        cpa16(base + 3 * ABYTES + so, Wl + bo);
    }
}

__global__ void __launch_bounds__(256, 2) gemm_bf(
    int layer, const float* __restrict__ mlp_b)
{
    extern __shared__ char dsm[];
    const __nv_bfloat16* Wh = g_wh + (size_t)layer * 256 * 512;
    const __nv_bfloat16* Wl = g_wl + (size_t)layer * 256 * 512;
    const float* bias = mlp_b + (size_t)layer * 256;

    int tid = threadIdx.x;
    int wid = tid >> 5, lane = tid & 31;
    int gid = lane >> 2, tig = lane & 3;
    int warp_m = wid >> 2, warp_n = wid & 3;
    int rowBase = blockIdx.y * 128;
    int colBase = blockIdx.x * 128;
    uint32_t sbase = smem_u32(dsm);

    float acc[4][4][4];
#pragma unroll
    for (int mi = 0; mi < 4; mi++)
#pragma unroll
        for (int ni = 0; ni < 4; ni++)
#pragma unroll
            for (int q = 0; q < 4; q++) acc[mi][ni][q] = 0.0f;

    stage_chunk(sbase, 0, rowBase, colBase, Wh, Wl, tid);
    asm volatile("cp.async.commit_group;");

    for (int c = 0; c < 16; c++) {
        asm volatile("cp.async.wait_group 0;");
        __syncthreads();   // ALSO proves all warps finished reading chunk c-1

        if (c + 1 < 16) {
            stage_chunk(sbase + ((c + 1) & 1) * STG, c + 1, rowBase, colBase,
                        Wh, Wl, tid);
            asm volatile("cp.async.commit_group;");
        }

        uint32_t sA  = sbase + (c & 1) * STG;
        uint32_t sAL = sA + ABYTES;
        uint32_t sB  = sA + 2 * ABYTES;
        uint32_t sBL = sA + 3 * ABYTES;
#pragma unroll
        for (int s = 0; s < 2; s++) {
            int kb = s * 16;
            uint32_t aH4[4][4], aL4[4][4], bH2[4][2], bL2[4][2];
            int rla = (lane & 15);
            int kha = (kb + ((lane >> 4) << 3)) * 2;
#pragma unroll
            for (int mi = 0; mi < 4; mi++) {
                uint32_t off = (uint32_t)((warp_m * 64 + mi * 16 + rla) * APITCH) + kha;
                LDSM4(aH4[mi][0], aH4[mi][1], aH4[mi][2], aH4[mi][3], sA + off);
                LDSM4(aL4[mi][0], aL4[mi][1], aL4[mi][2], aL4[mi][3], sAL + off);
            }
            int nlb = (lane & 7) + ((lane >> 4) << 3);
            int klb = (kb + (((lane >> 3) & 1) << 3)) * 2;
#pragma unroll
            for (int j = 0; j < 2; j++) {
                uint32_t off = (uint32_t)((warp_n * 32 + j * 16 + nlb) * APITCH) + klb;
                LDSM4(bH2[2 * j][0], bH2[2 * j][1], bH2[2 * j + 1][0], bH2[2 * j + 1][1], sB + off);
                LDSM4(bL2[2 * j][0], bL2[2 * j][1], bL2[2 * j + 1][0], bL2[2 * j + 1][1], sBL + off);
            }
#pragma unroll
            for (int mi = 0; mi < 4; mi++)
#pragma unroll
                for (int ni = 0; ni < 4; ni++) {
                    MMA16(acc[mi][ni], aH4[mi], bL2[ni][0], bL2[ni][1]);
                    MMA16(acc[mi][ni], aL4[mi], bH2[ni][0], bH2[ni][1]);
                    MMA16(acc[mi][ni], aH4[mi], bH2[ni][0], bH2[ni][1]);
                }
        }
    }

    // epilogue: bias + relu -> g_tmp, accumulating BN column partials
    float s1v[8], s2v[8];   // [ni*2+q]
#pragma unroll
    for (int j = 0; j < 8; j++) { s1v[j] = 0.f; s2v[j] = 0.f; }
#pragma unroll
    for (int mi = 0; mi < 4; mi++) {
        int r0 = rowBase + warp_m * 64 + mi * 16 + gid;
        int r1 = r0 + 8;
#pragma unroll
        for (int ni = 0; ni < 4; ni++) {
            int col = colBase + warp_n * 32 + ni * 8 + tig * 2;
            float b0 = __ldg(bias + col), b1 = __ldg(bias + col + 1);
            float v0 = fmaxf(acc[mi][ni][0] + b0, 0.0f);
            float v1 = fmaxf(acc[mi][ni][1] + b1, 0.0f);
            float v2 = fmaxf(acc[mi][ni][2] + b0, 0.0f);
            float v3 = fmaxf(acc[mi][ni][3] + b1, 0.0f);
            if (r0 < NN) {
                *(float2*)(g_tmp + (size_t)r0 * 256 + col) = make_float2(v0, v1);
                s1v[ni * 2 + 0] += v0; s2v[ni * 2 + 0] += v0 * v0;
                s1v[ni * 2 + 1] += v1; s2v[ni * 2 + 1] += v1 * v1;
            }
            if (r1 < NN) {
                *(float2*)(g_tmp + (size_t)r1 * 256 + col) = make_float2(v2, v3);
                s1v[ni * 2 + 0] += v2; s2v[ni * 2 + 0] += v2 * v2;
                s1v[ni * 2 + 1] += v3; s2v[ni * 2 + 1] += v3 * v3;
            }
        }
    }
    // reduce across gid (lane bits 2..4)
#pragma unroll
    for (int j = 0; j < 8; j++) {
#pragma unroll
        for (int m = 4; m <= 16; m <<= 1) {
            s1v[j] += __shfl_xor_sync(0xFFFFFFFF, s1v[j], m);
            s2v[j] += __shfl_xor_sync(0xFFFFFFFF, s2v[j], m);
        }
    }
    // stats staging in stage-0 smem region (safe: chunk 15 used stage 1)
    float* sm1 = (float*)dsm;            // [2][128]
    float* sm2 = sm1 + 256;              // [2][128]
    if (gid == 0) {
#pragma unroll
        for (int ni = 0; ni < 4; ni++)
#pragma unroll
            for (int q = 0; q < 2; q++) {
                int lc = warp_n * 32 + ni * 8 + tig * 2 + q;
                sm1[warp_m * 128 + lc] = s1v[ni * 2 + q];
                sm2[warp_m * 128 + lc] = s2v[ni * 2 + q];
            }
    }
    __syncthreads();
    if (tid < 128) {
        g_ps1[(size_t)blockIdx.y * 256 + colBase + tid] = sm1[tid] + sm1[128 + tid];
    } else {
        int t = tid - 128;
        g_ps2[(size_t)blockIdx.y * 256 + colBase + t] = sm2[t] + sm2[128 + t];
    }
}

// ---------------- BN reduce (parallel: one warp per column) --------------------
__global__ void __launch_bounds__(256) bnreduce_kernel() {
    int w = threadIdx.x >> 5;
    int lane = threadIdx.x & 31;
    int c = blockIdx.x * 8 + w;      // 32 blocks x 8 warps = 256 columns
    float s = 0.f, s2 = 0.f;
    for (int i = lane; i < NBY; i += 32) {
        s  += g_ps1[(size_t)i * 256 + c];
        s2 += g_ps2[(size_t)i * 256 + c];
    }
#pragma unroll
    for (int m = 16; m >= 1; m >>= 1) {
        s  += __shfl_xor_sync(0xFFFFFFFF, s, m);
        s2 += __shfl_xor_sync(0xFFFFFFFF, s2, m);
    }
    if (lane == 0) {
        g_cs[c] = s;
        g_cs2[c] = s2;
    }
}

// ---------------- BN apply -----------------------------------------------------
__global__ void __launch_bounds__(256) bnapply_kernel(
    float* __restrict__ out_ext, int use_ext,
    const float* __restrict__ gamma, const float* __restrict__ beta, int dorelu)
{
    int idx = blockIdx.x * blockDim.x + threadIdx.x;
    if (idx >= NN * HID / 4) return;
    float* O = use_ext ? out_ext : g_h;
    int c4 = idx & 63;
    const float invn = 1.0f / (float)NN;
    float4 cs  = ((const float4*)g_cs)[c4];
    float4 cs2 = ((const float4*)g_cs2)[c4];
    float4 gm  = ((const float4*)gamma)[c4];
    float4 bt  = ((const float4*)beta)[c4];
    float4 xv  = ((const float4*)g_tmp)[idx];
    float4 ov;
    {
        float mu = cs.x * invn, var = cs2.x * invn - mu * mu;
        ov.x = (xv.x - mu) * rsqrtf(var + BN_EPS) * gm.x + bt.x;
        mu = cs.y * invn; var = cs2.y * invn - mu * mu;
        ov.y = (xv.y - mu) * rsqrtf(var + BN_EPS) * gm.y + bt.y;
        mu = cs.z * invn; var = cs2.z * invn - mu * mu;
        ov.z = (xv.z - mu) * rsqrtf(var + BN_EPS) * gm.z + bt.z;
        mu = cs.w * invn; var = cs2.w * invn - mu * mu;
        ov.w = (xv.w - mu) * rsqrtf(var + BN_EPS) * gm.w + bt.w;
    }
    if (dorelu) {
        ov.x = fmaxf(ov.x, 0.0f); ov.y = fmaxf(ov.y, 0.0f);
        ov.z = fmaxf(ov.z, 0.0f); ov.w = fmaxf(ov.w, 0.0f);
    }
    ((float4*)O)[idx] = ov;
    if (!use_ext) {  // feed next layer's GEMM: bf16 hi/lo splits
        float h0, l0, h1, l1, h2, l2, h3, l3;
        bfsplit(ov.x, h0, l0); bfsplit(ov.y, h1, l1);
        bfsplit(ov.z, h2, l2); bfsplit(ov.w, h3, l3);
        ((uint2*)g_hh)[idx] = make_uint2(bfpack(h0, h1), bfpack(h2, h3));
        ((uint2*)g_hl)[idx] = make_uint2(bfpack(l0, l1), bfpack(l2, l3));
    }
}

// ---------------- launch ------------------------------------------------------
extern "C" void kernel_launch(void* const* d_in, const int* in_sizes, int n_in,
                              void* d_out, int out_size) {
    const float* x     = (const float*)d_in[0];
    const void*  ei    = d_in[1];
    const float* ea    = (const float*)d_in[2];
    const float* mlp_w = (const float*)d_in[3];
    const float* mlp_b = (const float*)d_in[4];
    const float* ew1   = (const float*)d_in[5];
    const float* ew2   = (const float*)d_in[6];
    const float* bn_g  = (const float*)d_in[7];
    const float* bn_b  = (const float*)d_in[8];
    float* out = (float*)d_out;

    cudaFuncSetAttribute(gemm_bf, cudaFuncAttributeMaxDynamicSharedMemorySize,
                         SMEM_DYN);

    detect_kernel<<<1, 256>>>((const int*)ei);
    zero_init_kernel<<<(NN * 4 + 255) / 256, 256>>>();
    count_kernel<<<(NE + 255) / 256, 256>>>(ei);
    scan1_kernel<<<NB_SCAN, 256>>>();
    scan2_kernel<<<1, 256>>>();
    scan3_kernel<<<NB_SCAN, 256>>>();
    fill_kernel<<<(NE + 255) / 256, 256>>>(ei);
    sedge_kernel<<<(NE + 255) / 256, 256>>>(ei, ea);
    wsplit_kernel<<<(NLAYERS * 512 * 256 + 255) / 256, 256>>>(mlp_w);
    xsplit_kernel<<<(NN * HID / 4 + 255) / 256, 256>>>(x);

    for (int l = 0; l < NLAYERS; l++) {
        int first = (l == 0) ? 1 : 0;
        int last  = (l == NLAYERS - 1) ? 1 : 0;

        agg_kernel<<<(NN * 32 + 255) / 256, 256>>>(
            x, first, ew1 + (size_t)l * 128, ew2 + (size_t)l * 3 * 128);

        dim3 ggrid(2, NBY);
        gemm_bf<<<ggrid, 256, SMEM_DYN>>>(l, mlp_b);

        bnreduce_kernel<<<32, 256>>>();
        bnapply_kernel<<<(NN * HID / 4 + 255) / 256, 256>>>(
            out, last, bn_g + (size_t)l * 256, bn_b + (size_t)l * 256, last ? 0 : 1);
    }
}